// round 13
// baseline (speedup 1.0000x reference)
#include <cuda_runtime.h>

#define D 1024
#define MAX_B 32
#define CHUNK 8
#define EPS 1e-6f
#define TRUNC 1e-9f

// 16-byte alignment REQUIRED: accessed as float4.
__device__ __align__(16) float g_state[MAX_B * D];   // zero at load; self-cleaning
__device__ __align__(16) float g_pool[MAX_B * D];
__device__ int g_arrive[MAX_B];                      // zero at load; self-cleaning
__device__ volatile int g_flag[MAX_B];               // pool-ready flags; self-cleaning
__device__ int g_fin[MAX_B];                         // gemv-done counters; self-cleaning

__device__ __forceinline__ float warp_sum(float v) {
#pragma unroll
    for (int o = 16; o > 0; o >>= 1) v += __shfl_xor_sync(0xffffffffu, v, o);
    return v;
}

// ---- Single kernel: scan -> per-batch pool -> per-batch GEMV (no global barrier)
// grid (NBX, B), 256 threads. Per-batch flag sync is deadlock-free without any
// co-residency assumption: spinners have already arrived at the counter.
__global__ void __launch_bounds__(256, 4)
fused_kernel(const float* __restrict__ x,
             const float* __restrict__ logit,
             const float* __restrict__ norm1_w,
             const float* __restrict__ norm2_w,
             const int* __restrict__ experts,
             const float* __restrict__ W,
             float* __restrict__ out, int S) {
    const int b = blockIdx.y;
    const int NBX = gridDim.x;
    const int tid = threadIdx.x;    // 256
    const int d0 = tid * 4;
    const int wid = tid >> 5, lane = tid & 31;

    // ---- chunk 0 loads FIRST: hide the decay prologue under memory ----
    const int c0 = blockIdx.x;
    int t_hi0 = S - 1 - c0 * CHUNK;
    float4 xr[CHUNK];
    if (t_hi0 >= 0) {
        int t_lo = t_hi0 - (CHUNK - 1);
        if (t_lo < 0) t_lo = 0;
        const int valid0 = t_hi0 - t_lo + 1;
        const float* xb = x + ((size_t)b * S + t_hi0) * D + d0;
#pragma unroll
        for (int i = 0; i < CHUNK; i++)
            xr[i] = (i < valid0) ? *(const float4*)(xb - (size_t)i * D)
                                 : make_float4(0.f, 0.f, 0.f, 0.f);
    } else {
#pragma unroll
        for (int i = 0; i < CHUNK; i++) xr[i] = make_float4(0.f, 0.f, 0.f, 0.f);
    }

    // ---- decay prologue (overlapped with loads above) ----
    const float4 lg = *(const float4*)&logit[d0];
    float4 dc4;
    dc4.x = 1.f / (1.f + __expf(-lg.x));
    dc4.y = 1.f / (1.f + __expf(-lg.y));
    dc4.z = 1.f / (1.f + __expf(-lg.z));
    dc4.w = 1.f / (1.f + __expf(-lg.w));

    __shared__ float smax[8];
    float m = fmaxf(fmaxf(dc4.x, dc4.y), fmaxf(dc4.z, dc4.w));
#pragma unroll
    for (int o = 16; o > 0; o >>= 1) m = fmaxf(m, __shfl_xor_sync(0xffffffffu, m, o));
    if (lane == 0) smax[wid] = m;
    __syncthreads();
    float maxd = fmaxf(fmaxf(smax[0], smax[1]), fmaxf(smax[2], smax[3]));
    maxd = fmaxf(maxd, fmaxf(fmaxf(smax[4], smax[5]), fmaxf(smax[6], smax[7])));

    const int sch = (S + CHUNK - 1) / CHUNK;
    int nch;
    if (maxd >= 0.9999995f) {
        nch = sch;
    } else {
        float K = logf(TRUNC) / logf(maxd);
        int Ki = (int)K + 2;
        nch = (Ki + CHUNK - 1) / CHUNK;
        if (nch > sch) nch = sch;
        if (nch < 1) nch = 1;
    }

    float4 acc = make_float4(0.f, 0.f, 0.f, 0.f);
    bool did = false;

    __shared__ float sred[CHUNK][8];
    __shared__ float srstd[CHUNK];

    for (int c = c0; c < nch; c += NBX) {
        did = true;
        const int t_hi = S - 1 - c * CHUNK;
        int t_lo = t_hi - (CHUNK - 1);
        if (t_lo < 0) t_lo = 0;
        const int valid = t_hi - t_lo + 1;
        const int e_min = c * CHUNK;

        if (c != c0) {
            const float* xb = x + ((size_t)b * S + t_hi) * D + d0;
#pragma unroll
            for (int i = 0; i < CHUNK; i++)
                xr[i] = (i < valid) ? *(const float4*)(xb - (size_t)i * D)
                                    : make_float4(0.f, 0.f, 0.f, 0.f);
        }

#pragma unroll
        for (int i = 0; i < CHUNK; i++) {
            float4 v = xr[i];
            float s = warp_sum(v.x * v.x + v.y * v.y + v.z * v.z + v.w * v.w);
            if (lane == 0) sred[i][wid] = s;
        }
        __syncthreads();
        if (tid < CHUNK) {
            float s = 0.f;
#pragma unroll
            for (int w = 0; w < 8; w++) s += sred[tid][w];
            srstd[tid] = rsqrtf(s * (1.f / D) + EPS);
        }
        __syncthreads();

        float4 w4;
        w4.x = __powf(dc4.x, (float)e_min);
        w4.y = __powf(dc4.y, (float)e_min);
        w4.z = __powf(dc4.z, (float)e_min);
        w4.w = __powf(dc4.w, (float)e_min);

#pragma unroll
        for (int i = 0; i < CHUNK; i++) {
            if (i < valid) {
                float r = srstd[i];
                acc.x += w4.x * xr[i].x * r;
                acc.y += w4.y * xr[i].y * r;
                acc.z += w4.z * xr[i].z * r;
                acc.w += w4.w * xr[i].w * r;
            }
            w4.x *= dc4.x; w4.y *= dc4.y; w4.z *= dc4.z; w4.w *= dc4.w;
        }
        __syncthreads();   // sred reuse
    }

    float* gs = &g_state[b * D + d0];
    if (did) {
        const float4 nw = *(const float4*)&norm1_w[d0];
        atomicAdd(gs + 0, acc.x * nw.x * (1.f - dc4.x));
        atomicAdd(gs + 1, acc.y * nw.y * (1.f - dc4.y));
        atomicAdd(gs + 2, acc.z * nw.z * (1.f - dc4.z));
        atomicAdd(gs + 3, acc.w * nw.w * (1.f - dc4.w));
    }

    __threadfence();
    __shared__ int s_last;
    if (tid == 0)
        s_last = (atomicAdd(&g_arrive[b], 1) == NBX - 1);
    __syncthreads();

    if (s_last) {
        // pool = rmsnorm(x[b,S-1] + state, norm2_w); reset state/arrive; set flag
        const float4 xl = *(const float4*)(x + ((size_t)b * S + (S - 1)) * D + d0);
        const float4 st = __ldcg((const float4*)gs);
        float4 v = make_float4(xl.x + st.x, xl.y + st.y, xl.z + st.z, xl.w + st.w);

        *(float4*)gs = make_float4(0.f, 0.f, 0.f, 0.f);
        if (tid == 0) g_arrive[b] = 0;

        float s = warp_sum(v.x * v.x + v.y * v.y + v.z * v.z + v.w * v.w);
        __shared__ float sm2[8];
        __shared__ float srs;
        if (lane == 0) sm2[wid] = s;
        __syncthreads();
        if (tid == 0) {
            float t = 0.f;
#pragma unroll
            for (int w = 0; w < 8; w++) t += sm2[w];
            srs = rsqrtf(t * (1.f / D) + EPS);
        }
        __syncthreads();

        const float r = srs;
        const float4 n2 = *(const float4*)&norm2_w[d0];
        float4 p = make_float4(v.x * r * n2.x, v.y * r * n2.y,
                               v.z * r * n2.z, v.w * r * n2.w);
        *(float4*)&g_pool[b * D + d0] = p;
        __threadfence();
        __syncthreads();
        if (tid == 0) g_flag[b] = 1;
    } else {
        // spin until batch b's pool is ready (deadlock-free: we already arrived)
        if (tid == 0) {
            while (g_flag[b] == 0) __nanosleep(32);
        }
        __syncthreads();
        __threadfence();   // acquire: order g_pool reads after flag observation
    }

    // ---- GEMV for batch b: out[b] = relu(W[experts[b]] @ pool[b]) ----
    const int e = experts[b];
    __shared__ __align__(16) float s_pool[D];   // 4 KB
    *(float4*)&s_pool[d0] = *(const float4*)&g_pool[b * D + d0];
    __syncthreads();

    const int gw = blockIdx.x * 8 + wid;       // global warp id, 0..NBX*8-1
    const int nwarp = NBX * 8;
    const float* We = W + (size_t)e * D * D;

    for (int row = gw; row < D; row += nwarp) {
        const float* Wr = We + (size_t)row * D;
        float4 w[8];
#pragma unroll
        for (int i = 0; i < 8; i++)
            w[i] = __ldg((const float4*)(Wr + i * 128 + lane * 4));
        float a = 0.f;
#pragma unroll
        for (int i = 0; i < 8; i++) {
            const float4 p = *(const float4*)&s_pool[i * 128 + lane * 4];
            a += w[i].x * p.x + w[i].y * p.y + w[i].z * p.z + w[i].w * p.w;
        }
        float s = warp_sum(a);
        if (lane == 0) out[b * D + row] = fmaxf(s, 0.f);
    }

    // ---- self-clean per-batch sync vars (last gemv finisher of batch b) ----
    __syncthreads();
    if (tid == 0) {
        __threadfence();
        if (atomicAdd(&g_fin[b], 1) == NBX - 1) {
            g_flag[b] = 0;
            g_fin[b] = 0;
        }
    }
}

// ---- Launch ----
extern "C" void kernel_launch(void* const* d_in, const int* in_sizes, int n_in,
                              void* d_out, int out_size) {
    const float* x        = (const float*)d_in[0];
    const int*   experts  = (const int*)d_in[1];
    const float* norm1_w  = (const float*)d_in[2];
    const float* tdl      = (const float*)d_in[3];
    const float* norm2_w  = (const float*)d_in[4];
    const float* W        = (const float*)d_in[5];
    float* out = (float*)d_out;

    const int B = in_sizes[1];
    const int S = in_sizes[0] / (B * D);

    int nbx = 24;
    if (nbx * B > 512) nbx = 512 / B;   // keep grid within one wave
    if (nbx < 1) nbx = 1;

    dim3 grid(nbx, B);
    fused_kernel<<<grid, 256>>>(x, tdl, norm1_w, norm2_w, experts, W, out, S);
}

// round 14
// speedup vs baseline: 1.0015x; 1.0015x over previous
#include <cuda_runtime.h>

#define D 1024
#define MAX_B 32
#define CHUNK 8
#define GRP 4
#define NBX 24
#define EPS 1e-6f
#define TRUNC 1e-9f

// 16-byte alignment REQUIRED: accessed as float4.
__device__ __align__(16) float g_state[MAX_B * D];   // zero at load; self-cleaning
__device__ __align__(16) float g_pool[MAX_B * D];
__device__ int g_arrive[MAX_B];                      // zero at load; self-cleaning

__device__ __forceinline__ float warp_sum(float v) {
#pragma unroll
    for (int o = 16; o > 0; o >>= 1) v += __shfl_xor_sync(0xffffffffu, v, o);
    return v;
}

// ---- Kernel 1: truncated decay-weighted scan + fused pool rmsnorm ----
__global__ void scan_kernel(const float* __restrict__ x,
                            const float* __restrict__ logit,
                            const float* __restrict__ norm1_w,
                            const float* __restrict__ norm2_w, int S) {
    const int b = blockIdx.y;
    const int tid = threadIdx.x;    // 256
    const int d0 = tid * 4;
    const int wid = tid >> 5, lane = tid & 31;

    // ---- chunk 0 loads FIRST: hide the decay prologue under memory ----
    const int c0 = blockIdx.x;
    int t_hi0 = S - 1 - c0 * CHUNK;
    float4 xr[CHUNK];
    if (t_hi0 >= 0) {
        int t_lo = t_hi0 - (CHUNK - 1);
        if (t_lo < 0) t_lo = 0;
        const int valid0 = t_hi0 - t_lo + 1;
        const float* xb = x + ((size_t)b * S + t_hi0) * D + d0;
#pragma unroll
        for (int i = 0; i < CHUNK; i++)
            xr[i] = (i < valid0) ? *(const float4*)(xb - (size_t)i * D)
                                 : make_float4(0.f, 0.f, 0.f, 0.f);
    } else {
#pragma unroll
        for (int i = 0; i < CHUNK; i++) xr[i] = make_float4(0.f, 0.f, 0.f, 0.f);
    }

    // ---- decay prologue (overlapped with loads above) ----
    const float4 lg = *(const float4*)&logit[d0];
    float4 dc4;
    dc4.x = 1.f / (1.f + __expf(-lg.x));
    dc4.y = 1.f / (1.f + __expf(-lg.y));
    dc4.z = 1.f / (1.f + __expf(-lg.z));
    dc4.w = 1.f / (1.f + __expf(-lg.w));

    __shared__ float smax[8];
    float m = fmaxf(fmaxf(dc4.x, dc4.y), fmaxf(dc4.z, dc4.w));
#pragma unroll
    for (int o = 16; o > 0; o >>= 1) m = fmaxf(m, __shfl_xor_sync(0xffffffffu, m, o));
    if (lane == 0) smax[wid] = m;
    __syncthreads();
    float maxd = fmaxf(fmaxf(smax[0], smax[1]), fmaxf(smax[2], smax[3]));
    maxd = fmaxf(maxd, fmaxf(fmaxf(smax[4], smax[5]), fmaxf(smax[6], smax[7])));

    const int sch = (S + CHUNK - 1) / CHUNK;
    int nch;
    if (maxd >= 0.9999995f) {
        nch = sch;
    } else {
        float K = logf(TRUNC) / logf(maxd);
        int Ki = (int)K + 2;
        nch = (Ki + CHUNK - 1) / CHUNK;
        if (nch > sch) nch = sch;
        if (nch < 1) nch = 1;
    }

    float4 acc = make_float4(0.f, 0.f, 0.f, 0.f);
    bool did = false;

    __shared__ float sred[CHUNK][8];
    __shared__ float srstd[CHUNK];

    for (int c = c0; c < nch; c += NBX) {
        did = true;
        const int t_hi = S - 1 - c * CHUNK;
        int t_lo = t_hi - (CHUNK - 1);
        if (t_lo < 0) t_lo = 0;
        const int valid = t_hi - t_lo + 1;
        const int e_min = c * CHUNK;

        if (c != c0) {   // chunk 0 already in registers
            const float* xb = x + ((size_t)b * S + t_hi) * D + d0;
#pragma unroll
            for (int i = 0; i < CHUNK; i++)
                xr[i] = (i < valid) ? *(const float4*)(xb - (size_t)i * D)
                                    : make_float4(0.f, 0.f, 0.f, 0.f);
        }

#pragma unroll
        for (int i = 0; i < CHUNK; i++) {
            float4 v = xr[i];
            float s = warp_sum(v.x * v.x + v.y * v.y + v.z * v.z + v.w * v.w);
            if (lane == 0) sred[i][wid] = s;
        }
        __syncthreads();
        if (tid < CHUNK) {
            float s = 0.f;
#pragma unroll
            for (int w = 0; w < 8; w++) s += sred[tid][w];
            srstd[tid] = rsqrtf(s * (1.f / D) + EPS);
        }
        __syncthreads();

        float4 w4;
        w4.x = __powf(dc4.x, (float)e_min);
        w4.y = __powf(dc4.y, (float)e_min);
        w4.z = __powf(dc4.z, (float)e_min);
        w4.w = __powf(dc4.w, (float)e_min);

#pragma unroll
        for (int i = 0; i < CHUNK; i++) {
            if (i < valid) {
                float r = srstd[i];
                acc.x += w4.x * xr[i].x * r;
                acc.y += w4.y * xr[i].y * r;
                acc.z += w4.z * xr[i].z * r;
                acc.w += w4.w * xr[i].w * r;
            }
            w4.x *= dc4.x; w4.y *= dc4.y; w4.z *= dc4.z; w4.w *= dc4.w;
        }
        __syncthreads();   // sred reuse
    }

    float* gs = &g_state[b * D + d0];
    if (did) {
        const float4 nw = *(const float4*)&norm1_w[d0];
        atomicAdd(gs + 0, acc.x * nw.x * (1.f - dc4.x));
        atomicAdd(gs + 1, acc.y * nw.y * (1.f - dc4.y));
        atomicAdd(gs + 2, acc.z * nw.z * (1.f - dc4.z));
        atomicAdd(gs + 3, acc.w * nw.w * (1.f - dc4.w));
    }

    __threadfence();
    __shared__ int s_last;
    if (tid == 0)
        s_last = (atomicAdd(&g_arrive[b], 1) == NBX - 1);
    __syncthreads();
    if (!s_last) return;

    const float4 xl = *(const float4*)(x + ((size_t)b * S + (S - 1)) * D + d0);
    const float4 st = __ldcg((const float4*)gs);
    float4 v = make_float4(xl.x + st.x, xl.y + st.y, xl.z + st.z, xl.w + st.w);

    *(float4*)gs = make_float4(0.f, 0.f, 0.f, 0.f);   // self-clean for replay
    if (tid == 0) g_arrive[b] = 0;

    float s = warp_sum(v.x * v.x + v.y * v.y + v.z * v.z + v.w * v.w);
    __shared__ float sm2[8];
    __shared__ float srs;
    if (lane == 0) sm2[wid] = s;
    __syncthreads();
    if (tid == 0) {
        float t = 0.f;
#pragma unroll
        for (int w = 0; w < 8; w++) t += sm2[w];
        srs = rsqrtf(t * (1.f / D) + EPS);
    }
    __syncthreads();

    const float r = srs;
    const float4 n2 = *(const float4*)&norm2_w[d0];
    float4 p = make_float4(v.x * r * n2.x, v.y * r * n2.y,
                           v.z * r * n2.z, v.w * r * n2.w);
    *(float4*)&g_pool[b * D + d0] = p;
}

// ---- Kernel 2: expert GEMV, 2048-block shape (R2-proven bandwidth).
// grid (D/8, E, ceil(B/GRP)). Early-exit empty z-groups BEFORE W loads
// (keeps W traffic ~16MB). W via __ldcg (single-use, skip L1). ----
__global__ void gemm_kernel(const int* __restrict__ experts,
                            const float* __restrict__ W,
                            float* __restrict__ out, int B) {
    const int e = blockIdx.y;
    const int g = blockIdx.z;
    const int tid = threadIdx.x;   // 256
    const int warp = tid >> 5, lane = tid & 31;

    // expert grouping from smem (fast) — must precede early-exit decision
    __shared__ int s_exp[MAX_B];
    __shared__ int s_bl[MAX_B];
    __shared__ int s_nb;
    if (tid < B) s_exp[tid] = experts[tid];
    __syncthreads();
    if (tid == 0) {
        int n = 0;
        for (int b = 0; b < B; b++)
            if (s_exp[b] == e) s_bl[n++] = b;
        s_nb = n;
    }
    __syncthreads();

    const int nb = s_nb;
    const int base = g * GRP;
    if (base >= nb) return;            // empty group: exit before W loads
    const int cnt = min(GRP, nb - base);

    // W row: 8 independent streaming LDG.128 (L2-only, single-use)
    const int row = blockIdx.x * 8 + warp;
    const float* Wr = W + ((size_t)e * D + row) * D;
    float4 w[8];
#pragma unroll
    for (int i = 0; i < 8; i++)
        w[i] = __ldcg((const float4*)(Wr + i * 128 + lane * 4));

    // stage this group's pool vectors in shared
    __shared__ __align__(16) float s_pool[GRP][D];   // 16 KB
#pragma unroll
    for (int j = 0; j < GRP; j++) {
        float4 p = make_float4(0.f, 0.f, 0.f, 0.f);
        if (j < cnt) p = *(const float4*)&g_pool[s_bl[base + j] * D + tid * 4];
        *(float4*)&s_pool[j][tid * 4] = p;
    }
    __syncthreads();

    float acc[GRP] = {0.f, 0.f, 0.f, 0.f};
#pragma unroll
    for (int i = 0; i < 8; i++) {
#pragma unroll
        for (int j = 0; j < GRP; j++) {
            const float4 p = *(const float4*)&s_pool[j][i * 128 + lane * 4];
            acc[j] += w[i].x * p.x + w[i].y * p.y + w[i].z * p.z + w[i].w * p.w;
        }
    }

#pragma unroll
    for (int j = 0; j < GRP; j++) {
        float s = warp_sum(acc[j]);
        if (lane == 0 && j < cnt)
            out[s_bl[base + j] * D + row] = fmaxf(s, 0.f);
    }
}

// ---- Launch ----
extern "C" void kernel_launch(void* const* d_in, const int* in_sizes, int n_in,
                              void* d_out, int out_size) {
    const float* x        = (const float*)d_in[0];
    const int*   experts  = (const int*)d_in[1];
    const float* norm1_w  = (const float*)d_in[2];
    const float* tdl      = (const float*)d_in[3];
    const float* norm2_w  = (const float*)d_in[4];
    const float* W        = (const float*)d_in[5];
    float* out = (float*)d_out;

    const int B = in_sizes[1];
    const int S = in_sizes[0] / (B * D);
    const int E = in_sizes[5] / (D * D);

    dim3 gscan(NBX, B);
    scan_kernel<<<gscan, 256>>>(x, tdl, norm1_w, norm2_w, S);

    dim3 ggemm(D / 8, E, (B + GRP - 1) / GRP);
    gemm_kernel<<<ggemm, 256>>>(experts, W, out, B);
}

// round 15
// speedup vs baseline: 1.1100x; 1.1083x over previous
#include <cuda_runtime.h>

#define D 1024
#define MAX_B 32
#define CHUNK 8
#define GRP 4
#define NBX 32
#define EPS 1e-6f
#define TRUNC 1e-9f

// 16-byte alignment REQUIRED: accessed as float4.
__device__ __align__(16) float g_state[MAX_B * D];   // zero at load; self-cleaning
__device__ __align__(16) float g_pool[MAX_B * D];
__device__ int g_arrive[MAX_B];                      // zero at load; self-cleaning

__device__ __forceinline__ float warp_sum(float v) {
#pragma unroll
    for (int o = 16; o > 0; o >>= 1) v += __shfl_xor_sync(0xffffffffu, v, o);
    return v;
}

// ---- Kernel 1 (round-9 scan, verbatim): truncated decay-weighted scan
//      + fused pool rmsnorm; chunk-0 loads hoisted above decay prologue ----
__global__ void scan_kernel(const float* __restrict__ x,
                            const float* __restrict__ logit,
                            const float* __restrict__ norm1_w,
                            const float* __restrict__ norm2_w, int S) {
    const int b = blockIdx.y;
    const int tid = threadIdx.x;    // 256
    const int d0 = tid * 4;
    const int wid = tid >> 5, lane = tid & 31;

    // ---- chunk 0 loads FIRST: hide the decay prologue under memory ----
    const int c0 = blockIdx.x;
    int t_hi0 = S - 1 - c0 * CHUNK;
    float4 xr[CHUNK];
    if (t_hi0 >= 0) {
        int t_lo = t_hi0 - (CHUNK - 1);
        if (t_lo < 0) t_lo = 0;
        const int valid0 = t_hi0 - t_lo + 1;
        const float* xb = x + ((size_t)b * S + t_hi0) * D + d0;
#pragma unroll
        for (int i = 0; i < CHUNK; i++)
            xr[i] = (i < valid0) ? *(const float4*)(xb - (size_t)i * D)
                                 : make_float4(0.f, 0.f, 0.f, 0.f);
    } else {
#pragma unroll
        for (int i = 0; i < CHUNK; i++) xr[i] = make_float4(0.f, 0.f, 0.f, 0.f);
    }

    // ---- decay prologue (overlapped with loads above) ----
    const float4 lg = *(const float4*)&logit[d0];
    float4 dc4;
    dc4.x = 1.f / (1.f + __expf(-lg.x));
    dc4.y = 1.f / (1.f + __expf(-lg.y));
    dc4.z = 1.f / (1.f + __expf(-lg.z));
    dc4.w = 1.f / (1.f + __expf(-lg.w));

    __shared__ float smax[8];
    float m = fmaxf(fmaxf(dc4.x, dc4.y), fmaxf(dc4.z, dc4.w));
#pragma unroll
    for (int o = 16; o > 0; o >>= 1) m = fmaxf(m, __shfl_xor_sync(0xffffffffu, m, o));
    if (lane == 0) smax[wid] = m;
    __syncthreads();
    float maxd = fmaxf(fmaxf(smax[0], smax[1]), fmaxf(smax[2], smax[3]));
    maxd = fmaxf(maxd, fmaxf(fmaxf(smax[4], smax[5]), fmaxf(smax[6], smax[7])));

    const int sch = (S + CHUNK - 1) / CHUNK;
    int nch;
    if (maxd >= 0.9999995f) {
        nch = sch;
    } else {
        float K = logf(TRUNC) / logf(maxd);
        int Ki = (int)K + 2;
        nch = (Ki + CHUNK - 1) / CHUNK;
        if (nch > sch) nch = sch;
        if (nch < 1) nch = 1;
    }

    float4 acc = make_float4(0.f, 0.f, 0.f, 0.f);
    bool did = false;

    __shared__ float sred[CHUNK][8];
    __shared__ float srstd[CHUNK];

    for (int c = c0; c < nch; c += NBX) {
        did = true;
        const int t_hi = S - 1 - c * CHUNK;
        int t_lo = t_hi - (CHUNK - 1);
        if (t_lo < 0) t_lo = 0;
        const int valid = t_hi - t_lo + 1;
        const int e_min = c * CHUNK;

        if (c != c0) {   // chunk 0 already in registers
            const float* xb = x + ((size_t)b * S + t_hi) * D + d0;
#pragma unroll
            for (int i = 0; i < CHUNK; i++)
                xr[i] = (i < valid) ? *(const float4*)(xb - (size_t)i * D)
                                    : make_float4(0.f, 0.f, 0.f, 0.f);
        }

#pragma unroll
        for (int i = 0; i < CHUNK; i++) {
            float4 v = xr[i];
            float s = warp_sum(v.x * v.x + v.y * v.y + v.z * v.z + v.w * v.w);
            if (lane == 0) sred[i][wid] = s;
        }
        __syncthreads();
        if (tid < CHUNK) {
            float s = 0.f;
#pragma unroll
            for (int w = 0; w < 8; w++) s += sred[tid][w];
            srstd[tid] = rsqrtf(s * (1.f / D) + EPS);
        }
        __syncthreads();

        float4 w4;
        w4.x = __powf(dc4.x, (float)e_min);
        w4.y = __powf(dc4.y, (float)e_min);
        w4.z = __powf(dc4.z, (float)e_min);
        w4.w = __powf(dc4.w, (float)e_min);

#pragma unroll
        for (int i = 0; i < CHUNK; i++) {
            if (i < valid) {
                float r = srstd[i];
                acc.x += w4.x * xr[i].x * r;
                acc.y += w4.y * xr[i].y * r;
                acc.z += w4.z * xr[i].z * r;
                acc.w += w4.w * xr[i].w * r;
            }
            w4.x *= dc4.x; w4.y *= dc4.y; w4.z *= dc4.z; w4.w *= dc4.w;
        }
        __syncthreads();   // sred reuse
    }

    float* gs = &g_state[b * D + d0];
    if (did) {
        const float4 nw = *(const float4*)&norm1_w[d0];
        atomicAdd(gs + 0, acc.x * nw.x * (1.f - dc4.x));
        atomicAdd(gs + 1, acc.y * nw.y * (1.f - dc4.y));
        atomicAdd(gs + 2, acc.z * nw.z * (1.f - dc4.z));
        atomicAdd(gs + 3, acc.w * nw.w * (1.f - dc4.w));
    }

    __threadfence();
    __shared__ int s_last;
    if (tid == 0)
        s_last = (atomicAdd(&g_arrive[b], 1) == NBX - 1);
    __syncthreads();
    if (!s_last) return;

    const float4 xl = *(const float4*)(x + ((size_t)b * S + (S - 1)) * D + d0);
    const float4 st = __ldcg((const float4*)gs);
    float4 v = make_float4(xl.x + st.x, xl.y + st.y, xl.z + st.z, xl.w + st.w);

    *(float4*)gs = make_float4(0.f, 0.f, 0.f, 0.f);   // self-clean for replay
    if (tid == 0) g_arrive[b] = 0;

    float s = warp_sum(v.x * v.x + v.y * v.y + v.z * v.z + v.w * v.w);
    __shared__ float sm2[8];
    __shared__ float srs;
    if (lane == 0) sm2[wid] = s;
    __syncthreads();
    if (tid == 0) {
        float t = 0.f;
#pragma unroll
        for (int w = 0; w < 8; w++) t += sm2[w];
        srs = rsqrtf(t * (1.f / D) + EPS);
    }
    __syncthreads();

    const float r = srs;
    const float4 n2 = *(const float4*)&norm2_w[d0];
    float4 p = make_float4(v.x * r * n2.x, v.y * r * n2.y,
                           v.z * r * n2.z, v.w * r * n2.w);
    *(float4*)&g_pool[b * D + d0] = p;
}

// ---- Kernel 2 (round-5 gemm, verbatim): expert-grouped GEMV,
//      1024 blocks, 2 rows/warp, depth-2 W prefetch, pool in shared ----
__global__ void gemm_kernel(const int* __restrict__ experts,
                            const float* __restrict__ W,
                            float* __restrict__ out, int B) {
    const int e = blockIdx.y;
    const int g = blockIdx.z;
    const int tid = threadIdx.x;   // 256

    __shared__ int s_exp[MAX_B];
    __shared__ int s_bl[MAX_B];
    __shared__ int s_nb;
    if (tid < B) s_exp[tid] = experts[tid];
    __syncthreads();
    if (tid == 0) {
        int n = 0;
        for (int b = 0; b < B; b++)
            if (s_exp[b] == e) s_bl[n++] = b;
        s_nb = n;
    }
    __syncthreads();

    const int nb = s_nb;
    const int base = g * GRP;
    if (base >= nb) return;
    const int cnt = min(GRP, nb - base);

    __shared__ __align__(16) float s_pool[GRP][D];   // 16 KB
#pragma unroll
    for (int j = 0; j < GRP; j++) {
        float4 p = make_float4(0.f, 0.f, 0.f, 0.f);
        if (j < cnt) p = *(const float4*)&g_pool[s_bl[base + j] * D + tid * 4];
        *(float4*)&s_pool[j][tid * 4] = p;
    }
    __syncthreads();

    const int warp = tid >> 5, lane = tid & 31;
    const int row0 = blockIdx.x * 16 + warp * 2;     // 2 rows per warp
    const float* W0 = W + ((size_t)e * D + row0) * D;
    const float* W1 = W0 + D;

    float acc0[GRP] = {0.f, 0.f, 0.f, 0.f};
    float acc1[GRP] = {0.f, 0.f, 0.f, 0.f};

    float4 a0 = __ldg((const float4*)(W0 + lane * 4));
    float4 a1 = __ldg((const float4*)(W1 + lane * 4));

#pragma unroll
    for (int i = 0; i < 8; i++) {
        float4 n0, n1;
        if (i < 7) {
            n0 = __ldg((const float4*)(W0 + (i + 1) * 128 + lane * 4));
            n1 = __ldg((const float4*)(W1 + (i + 1) * 128 + lane * 4));
        }
#pragma unroll
        for (int j = 0; j < GRP; j++) {
            const float4 p = *(const float4*)&s_pool[j][i * 128 + lane * 4];
            acc0[j] += a0.x * p.x + a0.y * p.y + a0.z * p.z + a0.w * p.w;
            acc1[j] += a1.x * p.x + a1.y * p.y + a1.z * p.z + a1.w * p.w;
        }
        if (i < 7) { a0 = n0; a1 = n1; }
    }

#pragma unroll
    for (int j = 0; j < GRP; j++) {
        float s0 = warp_sum(acc0[j]);
        float s1 = warp_sum(acc1[j]);
        if (lane == 0 && j < cnt) {
            const int ob = s_bl[base + j] * D;
            out[ob + row0]     = fmaxf(s0, 0.f);
            out[ob + row0 + 1] = fmaxf(s1, 0.f);
        }
    }
}

// ---- Launch ----
extern "C" void kernel_launch(void* const* d_in, const int* in_sizes, int n_in,
                              void* d_out, int out_size) {
    const float* x        = (const float*)d_in[0];
    const int*   experts  = (const int*)d_in[1];
    const float* norm1_w  = (const float*)d_in[2];
    const float* tdl      = (const float*)d_in[3];
    const float* norm2_w  = (const float*)d_in[4];
    const float* W        = (const float*)d_in[5];
    float* out = (float*)d_out;

    const int B = in_sizes[1];
    const int S = in_sizes[0] / (B * D);
    const int E = in_sizes[5] / (D * D);

    dim3 gscan(NBX, B);
    scan_kernel<<<gscan, 256>>>(x, tdl, norm1_w, norm2_w, S);

    dim3 ggemm(D / 16, E, (B + GRP - 1) / GRP);
    gemm_kernel<<<ggemm, 256>>>(experts, W, out, B);
}